// round 4
// baseline (speedup 1.0000x reference)
#include <cuda_runtime.h>
#include <math.h>

// Problem sizes (fixed by the reference)
#define BB 256
#define DD 512
#define HH 512

// Scratch: projections q,k,v,i,f,o  -> 6 * 256 * 512 * 4B = 3 MB
__device__ float g_proj[6][BB][HH];

struct GemmArgs {
    const float* x;        // [B, D] row-major
    const float* W[6];     // each [H, D] row-major (x @ W.T => dot of rows)
    const float* bias[3];  // b_i, b_f, b_o (for which = 3,4,5)
};

// ---- packed f32x2 helpers (sm_103a FFMA2; only reachable via PTX) ----
__device__ __forceinline__ unsigned long long bcast2(float a) {
    unsigned long long r;
    asm("mov.b64 %0, {%1, %1};" : "=l"(r) : "f"(a));
    return r;
}
__device__ __forceinline__ unsigned long long fma2(unsigned long long a,
                                                   unsigned long long b,
                                                   unsigned long long c) {
    unsigned long long d;
    asm("fma.rn.f32x2 %0, %1, %2, %3;" : "=l"(d) : "l"(a), "l"(b), "l"(c));
    return d;
}
__device__ __forceinline__ void unpack2(unsigned long long v, float& lo, float& hi) {
    asm("mov.b64 {%0, %1}, %2;" : "=f"(lo), "=f"(hi) : "l"(v));
}

// Fused 6-way projection GEMM: M=256, N=3072 (6*512), K=512.
// BM=64, BN=64, BK=16, 128 threads, 4x8 microtile using packed FFMA2.
// Each 64-wide N tile lies entirely within one weight matrix (64 | 512).
__global__ __launch_bounds__(128) void proj_kernel(GemmArgs a) {
    const int BK = 16;
    __shared__ float As[BK][64];   // As[k][m]
    __shared__ float Bs[BK][64];   // Bs[k][n]

    const int n_tile = blockIdx.x;           // 0..47
    const int m_tile = blockIdx.y;           // 0..3
    const int which  = (n_tile * 64) / HH;   // which weight matrix
    const int h0     = (n_tile * 64) % HH;   // column offset within that matrix
    const int row0   = m_tile * 64;

    const float* __restrict__ W = a.W[which];
    const float* __restrict__ x = a.x;

    const int tid  = threadIdx.x;
    // Loader mapping: 2 threads per row, each loads 2 float4s along K (16 floats/row)
    const int lrow = tid >> 1;          // 0..63
    const int lk   = (tid & 1) * 8;     // 0 or 8
    // Compute mapping: 16x8 thread grid of 4x8 micro-tiles
    const int tr = tid >> 3;            // 0..15 -> rows tr*4 .. +3
    const int tc = tid & 7;             // 0..7  -> cols tc*8 .. +7

    unsigned long long acc2[4][4];      // [i][jpair] packed pairs
#pragma unroll
    for (int i = 0; i < 4; i++)
#pragma unroll
        for (int j = 0; j < 4; j++) acc2[i][j] = 0ull;

    const float* gA = x + (size_t)(row0 + lrow) * DD + lk;
    const float* gB = W + (size_t)(h0 + lrow) * DD + lk;

    // Prologue: tile 0 -> regs
    float4 ra0 = *(const float4*)(gA + 0);
    float4 ra1 = *(const float4*)(gA + 4);
    float4 rb0 = *(const float4*)(gB + 0);
    float4 rb1 = *(const float4*)(gB + 4);

    const int T = DD / BK;  // 32 k-tiles
    for (int t = 0; t < T; t++) {
        // Store current regs -> smem (transposed)
        As[lk + 0][lrow] = ra0.x; As[lk + 1][lrow] = ra0.y;
        As[lk + 2][lrow] = ra0.z; As[lk + 3][lrow] = ra0.w;
        As[lk + 4][lrow] = ra1.x; As[lk + 5][lrow] = ra1.y;
        As[lk + 6][lrow] = ra1.z; As[lk + 7][lrow] = ra1.w;
        Bs[lk + 0][lrow] = rb0.x; Bs[lk + 1][lrow] = rb0.y;
        Bs[lk + 2][lrow] = rb0.z; Bs[lk + 3][lrow] = rb0.w;
        Bs[lk + 4][lrow] = rb1.x; Bs[lk + 5][lrow] = rb1.y;
        Bs[lk + 6][lrow] = rb1.z; Bs[lk + 7][lrow] = rb1.w;
        __syncthreads();

        // Prefetch next tile (gmem latency hidden by compute below)
        if (t + 1 < T) {
            const float* nA = gA + (t + 1) * BK;
            const float* nB = gB + (t + 1) * BK;
            ra0 = *(const float4*)(nA + 0);
            ra1 = *(const float4*)(nA + 4);
            rb0 = *(const float4*)(nB + 0);
            rb1 = *(const float4*)(nB + 4);
        }

        // Compute: 16 kk steps, each 16 packed FFMA2 (= 32 FMAs)
#pragma unroll
        for (int kk = 0; kk < BK; kk++) {
            const float4 av = *(const float4*)&As[kk][tr * 4];
            const float4 bv0 = *(const float4*)&Bs[kk][tc * 8];
            const float4 bv1 = *(const float4*)&Bs[kk][tc * 8 + 4];

            unsigned long long ap[4];
            ap[0] = bcast2(av.x); ap[1] = bcast2(av.y);
            ap[2] = bcast2(av.z); ap[3] = bcast2(av.w);

            unsigned long long bp[4];
            bp[0] = ((const unsigned long long*)&bv0)[0];
            bp[1] = ((const unsigned long long*)&bv0)[1];
            bp[2] = ((const unsigned long long*)&bv1)[0];
            bp[3] = ((const unsigned long long*)&bv1)[1];

#pragma unroll
            for (int i = 0; i < 4; i++)
#pragma unroll
                for (int j = 0; j < 4; j++)
                    acc2[i][j] = fma2(ap[i], bp[j], acc2[i][j]);
        }
        __syncthreads();
    }

    // Epilogue: optional bias + sigmoid for i/f/o, write to scratch
    const bool gate = (which >= 3);
    const float* __restrict__ bias = gate ? a.bias[which - 3] : nullptr;
#pragma unroll
    for (int i = 0; i < 4; i++) {
        const int r = row0 + tr * 4 + i;
#pragma unroll
        for (int j = 0; j < 4; j++) {
            float lo, hi;
            unpack2(acc2[i][j], lo, hi);
            const int h = h0 + tc * 8 + j * 2;
            if (gate) {
                lo += bias[h];
                hi += bias[h + 1];
                lo = 1.0f / (1.0f + __expf(-lo));
                hi = 1.0f / (1.0f + __expf(-hi));
            }
            g_proj[which][r][h]     = lo;
            g_proj[which][r][h + 1] = hi;
        }
    }
}

// Fused state update + readout.
// One warp per (b, i) row:
//   C_t[b,i,j] = f[b,i]*C_prev[b,i,j] + (i_t*k)[b,i]*v[b,j]
//   h_t[b,i]   = o[b,i] * tanh( sum_j C_t[b,i,j]*q[b,j] )
// Block: 512 threads = 16 warps -> 16 rows; grid (H/16, B).
__global__ __launch_bounds__(512) void update_kernel(const float* __restrict__ Cprev,
                                                     float* __restrict__ out_h,
                                                     float* __restrict__ out_C) {
    __shared__ float sv[HH];
    __shared__ float sq[HH];

    const int b   = blockIdx.y;
    const int i0  = blockIdx.x * 16;
    const int tid = threadIdx.x;

    // Stage v[b,:] and q[b,:] (shared across all 16 rows of this block)
    sv[tid] = g_proj[2][b][tid];
    sq[tid] = g_proj[0][b][tid];
    __syncthreads();

    const int warp = tid >> 5;
    const int lane = tid & 31;
    const int i    = i0 + warp;

    const float f_bi = g_proj[4][b][i];
    const float ik   = g_proj[3][b][i] * g_proj[1][b][i];
    const float o_bi = g_proj[5][b][i];

    const size_t rowoff = ((size_t)b * HH + i) * HH;
    const float4* __restrict__ Cp = (const float4*)(Cprev + rowoff);
    float4* __restrict__ Ct       = (float4*)(out_C + rowoff);
    const float4* __restrict__ v4 = (const float4*)sv;
    const float4* __restrict__ q4 = (const float4*)sq;

    float acc = 0.0f;
#pragma unroll
    for (int it = 0; it < 4; it++) {
        const int j4 = it * 32 + lane;    // 128 float4s per row
        float4 c = __ldcs(&Cp[j4]);       // stream: evict-first, C_prev never re-read
        const float4 vv = v4[j4];
        const float4 qq = q4[j4];
        c.x = fmaf(f_bi, c.x, ik * vv.x);
        c.y = fmaf(f_bi, c.y, ik * vv.y);
        c.z = fmaf(f_bi, c.z, ik * vv.z);
        c.w = fmaf(f_bi, c.w, ik * vv.w);
        __stcs(&Ct[j4], c);               // stream: C_t never re-read by this kernel
        acc += c.x * qq.x + c.y * qq.y + c.z * qq.z + c.w * qq.w;
    }

    // Warp reduction for the dot product
#pragma unroll
    for (int off = 16; off > 0; off >>= 1)
        acc += __shfl_xor_sync(0xFFFFFFFFu, acc, off);

    if (lane == 0) out_h[(size_t)b * HH + i] = o_bi * tanhf(acc);
}

extern "C" void kernel_launch(void* const* d_in, const int* in_sizes, int n_in,
                              void* d_out, int out_size) {
    // Inputs per metadata order:
    // 0:x 1:h_prev(unused) 2:C_prev 3:W_q 4:W_k 5:W_v 6:W_i 7:W_f 8:W_o 9:b_i 10:b_f 11:b_o
    const float* x     = (const float*)d_in[0];
    const float* Cprev = (const float*)d_in[2];

    GemmArgs a;
    a.x = x;
    a.W[0] = (const float*)d_in[3];  // W_q
    a.W[1] = (const float*)d_in[4];  // W_k
    a.W[2] = (const float*)d_in[5];  // W_v
    a.W[3] = (const float*)d_in[6];  // W_i
    a.W[4] = (const float*)d_in[7];  // W_f
    a.W[5] = (const float*)d_in[8];  // W_o
    a.bias[0] = (const float*)d_in[9];   // b_i
    a.bias[1] = (const float*)d_in[10];  // b_f
    a.bias[2] = (const float*)d_in[11];  // b_o

    float* out = (float*)d_out;
    float* out_h = out;                       // [B, H]
    float* out_C = out + (size_t)BB * HH;     // [B, H, H]

    dim3 gGemm(48, 4);            // N tiles (3072/64), M tiles (256/64)
    proj_kernel<<<gGemm, 128>>>(a);

    dim3 gUpd(HH / 16, BB);       // (32, 256) blocks, 512 threads
    update_kernel<<<gUpd, 512>>>(Cprev, out_h, out_C);
}

// round 5
// speedup vs baseline: 1.2397x; 1.2397x over previous
#include <cuda_runtime.h>
#include <math.h>

// Problem sizes (fixed by the reference)
#define BB 256
#define DD 512
#define HH 512

// Scratch: projections q,k,v,i,f,o  -> 6 * 256 * 512 * 4B = 3 MB
__device__ float g_proj[6][BB][HH];

struct GemmArgs {
    const float* x;        // [B, D] row-major
    const float* W[6];     // each [H, D] row-major (x @ W.T => dot of rows)
    const float* bias[3];  // b_i, b_f, b_o (for which = 3,4,5)
};

// Fused 6-way projection GEMM: M=256, N=3072 (6*512), K=512.
// BM=64, BN=64, BK=16, 256 threads, 4x4 microtile.
// Double-buffered smem: ONE __syncthreads per k-tile; next gmem tile is
// prefetched into registers while computing on the current smem buffer.
__global__ __launch_bounds__(256) void proj_kernel(GemmArgs a) {
    const int BK = 16;
    __shared__ float As[2][BK][64];   // As[buf][k][m]
    __shared__ float Bs[2][BK][64];   // Bs[buf][k][n]

    const int n_tile = blockIdx.x;           // 0..47
    const int m_tile = blockIdx.y;           // 0..3
    const int which  = (n_tile * 64) / HH;   // which weight matrix
    const int h0     = (n_tile * 64) % HH;   // column offset within that matrix
    const int row0   = m_tile * 64;

    const float* __restrict__ W = a.W[which];
    const float* __restrict__ x = a.x;

    const int tid  = threadIdx.x;
    // Loader mapping: 4 threads per row, each one float4 along K
    const int lrow = tid >> 2;         // 0..63
    const int lk   = (tid & 3) * 4;    // 0,4,8,12
    // Compute mapping: 16x16 thread grid of 4x4 micro-tiles
    const int tr = tid >> 4;           // 0..15 -> rows tr*4..+3
    const int tc = tid & 15;           // 0..15 -> cols tc*4..+3

    float acc[4][4];
#pragma unroll
    for (int i = 0; i < 4; i++)
#pragma unroll
        for (int j = 0; j < 4; j++) acc[i][j] = 0.0f;

    const float* gA = x + (size_t)(row0 + lrow) * DD + lk;
    const float* gB = W + (size_t)(h0 + lrow) * DD + lk;

    // Prologue: tile 0 gmem -> regs -> smem buf 0
    float4 ra = *(const float4*)gA;
    float4 rb = *(const float4*)gB;
    As[0][lk + 0][lrow] = ra.x; As[0][lk + 1][lrow] = ra.y;
    As[0][lk + 2][lrow] = ra.z; As[0][lk + 3][lrow] = ra.w;
    Bs[0][lk + 0][lrow] = rb.x; Bs[0][lk + 1][lrow] = rb.y;
    Bs[0][lk + 2][lrow] = rb.z; Bs[0][lk + 3][lrow] = rb.w;
    __syncthreads();

    const int T = DD / BK;  // 32 k-tiles
#pragma unroll 1
    for (int t = 0; t < T; t++) {
        const int cur = t & 1;
        const int nxt = cur ^ 1;

        // Prefetch tile t+1 into registers (latency overlapped with compute)
        if (t + 1 < T) {
            ra = *(const float4*)(gA + (t + 1) * BK);
            rb = *(const float4*)(gB + (t + 1) * BK);
        }

        // Compute on current buffer: 16 kk steps x 16 FFMA
#pragma unroll
        for (int kk = 0; kk < BK; kk++) {
            const float4 av = *(const float4*)&As[cur][kk][tr * 4];
            const float4 bv = *(const float4*)&Bs[cur][kk][tc * 4];
            const float ar[4] = {av.x, av.y, av.z, av.w};
            const float br[4] = {bv.x, bv.y, bv.z, bv.w};
#pragma unroll
            for (int i = 0; i < 4; i++)
#pragma unroll
                for (int j = 0; j < 4; j++) acc[i][j] = fmaf(ar[i], br[j], acc[i][j]);
        }

        // Stage prefetched tile into the other buffer (no reader of nxt yet)
        if (t + 1 < T) {
            As[nxt][lk + 0][lrow] = ra.x; As[nxt][lk + 1][lrow] = ra.y;
            As[nxt][lk + 2][lrow] = ra.z; As[nxt][lk + 3][lrow] = ra.w;
            Bs[nxt][lk + 0][lrow] = rb.x; Bs[nxt][lk + 1][lrow] = rb.y;
            Bs[nxt][lk + 2][lrow] = rb.z; Bs[nxt][lk + 3][lrow] = rb.w;
        }
        __syncthreads();   // one barrier per tile: nxt writes visible, cur reads done
    }

    // Epilogue: optional bias + sigmoid for i/f/o, write to scratch
    const bool gate = (which >= 3);
    const float* __restrict__ bias = gate ? a.bias[which - 3] : nullptr;
#pragma unroll
    for (int i = 0; i < 4; i++) {
        const int r = row0 + tr * 4 + i;
#pragma unroll
        for (int j = 0; j < 4; j++) {
            const int h = h0 + tc * 4 + j;
            float v = acc[i][j];
            if (gate) {
                v += bias[h];
                v = 1.0f / (1.0f + __expf(-v));
            }
            g_proj[which][r][h] = v;
        }
    }
}

// Fused state update + readout (R1 version — plain ld/st; .cs hints regressed).
// One warp per (b, i) row:
//   C_t[b,i,j] = f[b,i]*C_prev[b,i,j] + (i_t*k)[b,i]*v[b,j]
//   h_t[b,i]   = o[b,i] * tanh( sum_j C_t[b,i,j]*q[b,j] )
// Block: 512 threads = 16 warps -> 16 rows; grid (H/16, B).
__global__ __launch_bounds__(512) void update_kernel(const float* __restrict__ Cprev,
                                                     float* __restrict__ out_h,
                                                     float* __restrict__ out_C) {
    __shared__ float sv[HH];
    __shared__ float sq[HH];

    const int b   = blockIdx.y;
    const int i0  = blockIdx.x * 16;
    const int tid = threadIdx.x;

    // Stage v[b,:] and q[b,:] (shared across all 16 rows of this block)
    sv[tid] = g_proj[2][b][tid];
    sq[tid] = g_proj[0][b][tid];
    __syncthreads();

    const int warp = tid >> 5;
    const int lane = tid & 31;
    const int i    = i0 + warp;

    const float f_bi = g_proj[4][b][i];
    const float ik   = g_proj[3][b][i] * g_proj[1][b][i];
    const float o_bi = g_proj[5][b][i];

    const size_t rowoff = ((size_t)b * HH + i) * HH;
    const float4* __restrict__ Cp = (const float4*)(Cprev + rowoff);
    float4* __restrict__ Ct       = (float4*)(out_C + rowoff);
    const float4* __restrict__ v4 = (const float4*)sv;
    const float4* __restrict__ q4 = (const float4*)sq;

    float acc = 0.0f;
#pragma unroll
    for (int it = 0; it < 4; it++) {
        const int j4 = it * 32 + lane;    // 128 float4s per row
        float4 c = Cp[j4];
        const float4 vv = v4[j4];
        const float4 qq = q4[j4];
        c.x = fmaf(f_bi, c.x, ik * vv.x);
        c.y = fmaf(f_bi, c.y, ik * vv.y);
        c.z = fmaf(f_bi, c.z, ik * vv.z);
        c.w = fmaf(f_bi, c.w, ik * vv.w);
        Ct[j4] = c;
        acc += c.x * qq.x + c.y * qq.y + c.z * qq.z + c.w * qq.w;
    }

    // Warp reduction for the dot product
#pragma unroll
    for (int off = 16; off > 0; off >>= 1)
        acc += __shfl_xor_sync(0xFFFFFFFFu, acc, off);

    if (lane == 0) out_h[(size_t)b * HH + i] = o_bi * tanhf(acc);
}

extern "C" void kernel_launch(void* const* d_in, const int* in_sizes, int n_in,
                              void* d_out, int out_size) {
    // Inputs per metadata order:
    // 0:x 1:h_prev(unused) 2:C_prev 3:W_q 4:W_k 5:W_v 6:W_i 7:W_f 8:W_o 9:b_i 10:b_f 11:b_o
    const float* x     = (const float*)d_in[0];
    const float* Cprev = (const float*)d_in[2];

    GemmArgs a;
    a.x = x;
    a.W[0] = (const float*)d_in[3];  // W_q
    a.W[1] = (const float*)d_in[4];  // W_k
    a.W[2] = (const float*)d_in[5];  // W_v
    a.W[3] = (const float*)d_in[6];  // W_i
    a.W[4] = (const float*)d_in[7];  // W_f
    a.W[5] = (const float*)d_in[8];  // W_o
    a.bias[0] = (const float*)d_in[9];   // b_i
    a.bias[1] = (const float*)d_in[10];  // b_f
    a.bias[2] = (const float*)d_in[11];  // b_o

    float* out = (float*)d_out;
    float* out_h = out;                       // [B, H]
    float* out_C = out + (size_t)BB * HH;     // [B, H, H]

    dim3 gGemm(48, 4);            // N tiles (3072/64), M tiles (256/64)
    proj_kernel<<<gGemm, 256>>>(a);

    dim3 gUpd(HH / 16, BB);       // (32, 256) blocks, 512 threads
    update_kernel<<<gUpd, 512>>>(Cprev, out_h, out_C);
}